// round 6
// baseline (speedup 1.0000x reference)
#include <cuda_runtime.h>
#include <cstdint>

#define T_LEN   1000000
#define HIDDEN  75
#define NS      16
#define BS      64                 // steps per checkpoint block
#define NBLK    (T_LEN / BS)       // 15625
#define RB      8                  // ring blocks (smem)

// Scratch: negated log-priors in EVEN/ODD-permuted layout per step:
//   arr[0..7]  = np_{0,2,4,...,14}  (E half)
//   arr[8..15] = np_{1,3,5,...,15}  (O half)
// and 8-state checkpoints in NATURAL order [p0..p7].
__device__ float g_np[T_LEN * 16];     // 64 MB
__device__ float g_ckpt[NBLK * 8];     // 500 KB

__device__ __forceinline__ int ld_acq(const int* p) {
    int v;
    asm volatile("ld.acquire.cta.b32 %0, [%1];" : "=r"(v) : "l"(p) : "memory");
    return v;
}
__device__ __forceinline__ void st_rel(int* p, int v) {
    asm volatile("st.release.cta.b32 [%0], %1;" :: "l"(p), "r"(v) : "memory");
}

// ================= K1: priors =================
// Replays reference op order: mul+add+relu, fma-accumulate ascending j,
// +b2, max, shift, sequential exp-sum, log. Stores NEGATED log_softmax,
// permuted into E/O halves.
__global__ void k_priors(const float* __restrict__ rx,
                         const float* __restrict__ W1,
                         const float* __restrict__ b1,
                         const float* __restrict__ W2,
                         const float* __restrict__ b2,
                         int T) {
    __shared__ float sW1[HIDDEN], sb1[HIDDEN], sW2[HIDDEN * NS], sb2[NS];
    for (int i = threadIdx.x; i < HIDDEN; i += blockDim.x) { sW1[i] = W1[i]; sb1[i] = b1[i]; }
    for (int i = threadIdx.x; i < HIDDEN * NS; i += blockDim.x) sW2[i] = W2[i];
    if (threadIdx.x < NS) sb2[threadIdx.x] = b2[threadIdx.x];
    __syncthreads();

    int t = blockIdx.x * blockDim.x + threadIdx.x;
    if (t >= T) return;

    float x = rx[t];
    float acc[NS];
#pragma unroll
    for (int i = 0; i < NS; i++) acc[i] = 0.0f;

    for (int j = 0; j < HIDDEN; j++) {
        float h = __fadd_rn(__fmul_rn(x, sW1[j]), sb1[j]);
        h = fmaxf(h, 0.0f);
#pragma unroll
        for (int i = 0; i < NS; i++) acc[i] = fmaf(h, sW2[j * NS + i], acc[i]);
    }
#pragma unroll
    for (int i = 0; i < NS; i++) acc[i] = __fadd_rn(acc[i], sb2[i]);

    float m = acc[0];
#pragma unroll
    for (int i = 1; i < NS; i++) m = fmaxf(m, acc[i]);

    float sh[NS];
    float s = 0.0f;
#pragma unroll
    for (int i = 0; i < NS; i++) {
        sh[i] = __fadd_rn(acc[i], -m);
        s = __fadd_rn(s, expf(sh[i]));
    }
    float L = logf(s);

    float* dst = g_np + (size_t)t * NS;
#pragma unroll
    for (int i = 0; i < 8; i++) {
        dst[i]     = __fadd_rn(L, -sh[2 * i]);       // E half: np_{2i}
        dst[8 + i] = __fadd_rn(L, -sh[2 * i + 1]);   // O half: np_{2i+1}
    }
}

// ================= K2: exact sequential scan =================
// Warp 0: state as 8 scalar floats s0..s7. Per step:
//   pairs A=(s0,s2) B=(s4,s6) C=(s1,s3) D=(s5,s7)  (4 mov.b64, elidable)
//   w_k = FFMA2(pair, (1,1), npE-pair)   — bit-equal to FADD (proven)
//   x_k = FFMA2(pair, (1,1), npO-pair)
//   s_i = min.f32(w half, x half)        — writes straight into state
// Unpack movs are pure register renaming. Worst-case PTX ops/step = 32.
// Warps 1-3: stage priors global->smem ring (own SMSPs; spins steal no scan slots).
__global__ void __launch_bounds__(128, 1) k_scan() {
    __shared__ __align__(16) float ring[RB * BS * 16];   // 32 KB
    __shared__ int flag[RB];
    __shared__ int consumed;

    const int tid  = threadIdx.x;
    const int wid  = tid >> 5;
    const int lane = tid & 31;

    if (tid < RB) flag[tid] = 0;
    if (tid == 0) consumed = 0;
    __syncthreads();

    if (wid == 0) {
        float s0 = 0.f, s1 = 0.f, s2 = 0.f, s3 = 0.f, s4 = 0.f, s5 = 0.f, s6 = 0.f, s7 = 0.f;
        const unsigned long long ONE = 0x3F8000003F800000ULL;        // (1.0f,1.0f)
        for (int b = 0; b < NBLK; b++) {
            if (lane == 0) {
                float4* cp = (float4*)(g_ckpt + (size_t)b * 8);
                cp[0] = make_float4(s0, s1, s2, s3);
                cp[1] = make_float4(s4, s5, s6, s7);
            }
            while (ld_acq(&flag[b & (RB - 1)]) != b + 1) { }
            unsigned sbase = (unsigned)__cvta_generic_to_shared(&ring[(b & (RB - 1)) * (BS * 16)]);
#pragma unroll 1
            for (int kk = 0; kk < BS; kk += 16) {
#pragma unroll
                for (int k2 = 0; k2 < 16; k2++) {
                    unsigned addr = sbase + (kk + k2) * 64;
                    asm("{\n\t"
                        ".reg .b64 A,B,C,D;\n\t"
                        ".reg .b64 ne0,ne1,ne2,ne3,no0,no1,no2,no3;\n\t"
                        ".reg .b64 w0,w1,w2,w3,x0,x1,x2,x3;\n\t"
                        ".reg .f32 w0l,w0h,w1l,w1h,w2l,w2h,w3l,w3h;\n\t"
                        ".reg .f32 x0l,x0h,x1l,x1h,x2l,x2h,x3l,x3h;\n\t"
                        "ld.shared.v2.u64 {ne0,ne1}, [%8];\n\t"
                        "ld.shared.v2.u64 {ne2,ne3}, [%8+16];\n\t"
                        "ld.shared.v2.u64 {no0,no1}, [%8+32];\n\t"
                        "ld.shared.v2.u64 {no2,no3}, [%8+48];\n\t"
                        "mov.b64 A, {%0,%2};\n\t"
                        "mov.b64 B, {%4,%6};\n\t"
                        "mov.b64 C, {%1,%3};\n\t"
                        "mov.b64 D, {%5,%7};\n\t"
                        "fma.rn.f32x2 w0, A, %9, ne0;\n\t"
                        "fma.rn.f32x2 w1, B, %9, ne1;\n\t"
                        "fma.rn.f32x2 w2, A, %9, ne2;\n\t"
                        "fma.rn.f32x2 w3, B, %9, ne3;\n\t"
                        "fma.rn.f32x2 x0, C, %9, no0;\n\t"
                        "fma.rn.f32x2 x1, D, %9, no1;\n\t"
                        "fma.rn.f32x2 x2, C, %9, no2;\n\t"
                        "fma.rn.f32x2 x3, D, %9, no3;\n\t"
                        "mov.b64 {w0l,w0h}, w0;\n\t"
                        "mov.b64 {w1l,w1h}, w1;\n\t"
                        "mov.b64 {w2l,w2h}, w2;\n\t"
                        "mov.b64 {w3l,w3h}, w3;\n\t"
                        "mov.b64 {x0l,x0h}, x0;\n\t"
                        "mov.b64 {x1l,x1h}, x1;\n\t"
                        "mov.b64 {x2l,x2h}, x2;\n\t"
                        "mov.b64 {x3l,x3h}, x3;\n\t"
                        "min.f32 %0, w0l, x0l;\n\t"   // pn0
                        "min.f32 %1, w0h, x0h;\n\t"   // pn1
                        "min.f32 %2, w1l, x1l;\n\t"   // pn2
                        "min.f32 %3, w1h, x1h;\n\t"   // pn3
                        "min.f32 %4, w2l, x2l;\n\t"   // pn4
                        "min.f32 %5, w2h, x2h;\n\t"   // pn5
                        "min.f32 %6, w3l, x3l;\n\t"   // pn6
                        "min.f32 %7, w3h, x3h;\n\t"   // pn7
                        "}"
                        : "+f"(s0), "+f"(s1), "+f"(s2), "+f"(s3),
                          "+f"(s4), "+f"(s5), "+f"(s6), "+f"(s7)
                        : "r"(addr), "l"(ONE)
                        : "memory");
                }
            }
            if (lane == 0) st_rel(&consumed, b + 1);
        }
    } else {
        // copier warps: wid 1..3 handle blocks b with b % 3 == wid-1
        for (int b = wid - 1; b < NBLK; b += 3) {
            while (b >= RB && ld_acq(&consumed) < b - RB + 1) __nanosleep(100);
            const float4* src = (const float4*)(g_np + (size_t)b * (BS * 16));
            float4* dst = (float4*)&ring[(b & (RB - 1)) * (BS * 16)];
#pragma unroll
            for (int r = 0; r < 8; r++) dst[r * 32 + lane] = src[r * 32 + lane];
            __syncwarp();
            if (lane == 0) st_rel(&flag[b & (RB - 1)], b + 1);
        }
    }
}

// ================= K3: parallel det/conf emission =================
// Each thread replays one 64-step chunk bit-exactly from its checkpoint.
// Checkpoint layout: natural [p0..p7]; np layout: E half then O half.
__global__ void k_emit(float* __restrict__ out_det, float* __restrict__ out_conf) {
    int c = blockIdx.x * blockDim.x + threadIdx.x;
    if (c >= NBLK) return;

    float p[8];
    float4 a = *(const float4*)(g_ckpt + (size_t)c * 8);
    float4 b = *(const float4*)(g_ckpt + (size_t)c * 8 + 4);
    p[0] = a.x; p[1] = a.y; p[2] = a.z; p[3] = a.w;
    p[4] = b.x; p[5] = b.y; p[6] = b.z; p[7] = b.w;

    const float* np = g_np + (size_t)c * (BS * 16);
    const int tbase = c * BS;

    for (int k = 0; k < BS; k++) {
        // det: first-index argmin over p[0..7], parity
        float best = p[0];
        int idx = 0;
#pragma unroll
        for (int j = 1; j < 8; j++) {
            if (p[j] < best) { best = p[j]; idx = j; }
        }
        // conf: S = sum_{j=0..15} exp(pmin - p_j) with duplicated halves,
        // sequential ascending; 2*conf = 2*(1/S)
        float e[8];
#pragma unroll
        for (int j = 0; j < 8; j++) e[j] = expf(__fadd_rn(best, -p[j]));
        float S = e[0];
#pragma unroll
        for (int j = 1; j < 8; j++) S = __fadd_rn(S, e[j]);
#pragma unroll
        for (int j = 0; j < 8; j++) S = __fadd_rn(S, e[j]);
        float conf = __fdiv_rn(1.0f, S);

        out_det[tbase + k]  = (float)(idx & 1);
        out_conf[tbase + k] = __fmul_rn(2.0f, conf);

        // update, identical arithmetic to K2 packed ops:
        // p_new[i] = min(p[(2i)&7] + E_i, p[((2i)&7)+1] + O_i)
        const float* q = np + k * 16;
        float4 q0 = *(const float4*)(q);       // E0..E3
        float4 q1 = *(const float4*)(q + 4);   // E4..E7
        float4 q2 = *(const float4*)(q + 8);   // O0..O3
        float4 q3 = *(const float4*)(q + 12);  // O4..O7
        float E[8] = { q0.x, q0.y, q0.z, q0.w,  q1.x, q1.y, q1.z, q1.w };
        float O[8] = { q2.x, q2.y, q2.z, q2.w,  q3.x, q3.y, q3.z, q3.w };
        float newp[8];
#pragma unroll
        for (int i = 0; i < 8; i++) {
            int a2 = (2 * i) & 7;
            newp[i] = fminf(__fadd_rn(p[a2],     E[i]),
                            __fadd_rn(p[a2 + 1], O[i]));
        }
#pragma unroll
        for (int i = 0; i < 8; i++) p[i] = newp[i];
    }
}

// ================= launch =================
extern "C" void kernel_launch(void* const* d_in, const int* in_sizes, int n_in,
                              void* d_out, int out_size) {
    const float* rx = (const float*)d_in[0];
    const float* W1 = (const float*)d_in[1];
    const float* b1 = (const float*)d_in[2];
    const float* W2 = (const float*)d_in[3];
    const float* b2 = (const float*)d_in[4];
    float* out = (float*)d_out;

    int T = in_sizes[0];
    if (T > T_LEN) T = T_LEN;

    k_priors<<<(T + 255) / 256, 256>>>(rx, W1, b1, W2, b2, T);
    k_scan<<<1, 128>>>();
    k_emit<<<(NBLK + 127) / 128, 128>>>(out, out + T);
}

// round 7
// speedup vs baseline: 1.2055x; 1.2055x over previous
#include <cuda_runtime.h>
#include <cstdint>

#define T_LEN   1000000
#define HIDDEN  75
#define NS      16
#define BS      64                 // steps per checkpoint block
#define NBLK    (T_LEN / BS)       // 15625
#define NREC    (T_LEN / 2)        // double-step records
#define RB      8                  // ring blocks (smem)

// g_np: per double-step records of 32 floats (negated log-priors, permuted):
//  lane0: [np[t][0..3]] [np[t][8..11]] [np[t+1][0],[1],[8],[9]] [np[t+1][4],[5],[12],[13]]
//  lane1: [np[t][5],[4],[7],[6]] [np[t][13],[12],[15],[14]]
//         [np[t+1][10],[11],[2],[3]] [np[t+1][14],[15],[6],[7]]
// g_ckpt: per block, lane0 stores (p0,p1,p2,p3), lane1 stores (p5,p4,p7,p6).
__device__ float g_np[T_LEN * 16];     // 64 MB (NREC * 32)
__device__ float g_ckpt[NBLK * 8];     // 500 KB

__device__ __forceinline__ int ld_acq(const int* p) {
    int v;
    asm volatile("ld.acquire.cta.b32 %0, [%1];" : "=r"(v) : "l"(p) : "memory");
    return v;
}
__device__ __forceinline__ void st_rel(int* p, int v) {
    asm volatile("st.release.cta.b32 [%0], %1;" :: "l"(p), "r"(v) : "memory");
}

// ================= K1: priors =================
// Replays reference op order exactly (mul+add+relu, fma ascending, +b2, max,
// shift, sequential exp-sum, log); writes negated log_softmax into the
// per-lane permuted double-step record layout.
__global__ void k_priors(const float* __restrict__ rx,
                         const float* __restrict__ W1,
                         const float* __restrict__ b1,
                         const float* __restrict__ W2,
                         const float* __restrict__ b2,
                         int T) {
    __shared__ float sW1[HIDDEN], sb1[HIDDEN], sW2[HIDDEN * NS], sb2[NS];
    for (int i = threadIdx.x; i < HIDDEN; i += blockDim.x) { sW1[i] = W1[i]; sb1[i] = b1[i]; }
    for (int i = threadIdx.x; i < HIDDEN * NS; i += blockDim.x) sW2[i] = W2[i];
    if (threadIdx.x < NS) sb2[threadIdx.x] = b2[threadIdx.x];
    __syncthreads();

    int t = blockIdx.x * blockDim.x + threadIdx.x;
    if (t >= T) return;

    float x = rx[t];
    float acc[NS];
#pragma unroll
    for (int i = 0; i < NS; i++) acc[i] = 0.0f;

    for (int j = 0; j < HIDDEN; j++) {
        float h = __fadd_rn(__fmul_rn(x, sW1[j]), sb1[j]);
        h = fmaxf(h, 0.0f);
#pragma unroll
        for (int i = 0; i < NS; i++) acc[i] = fmaf(h, sW2[j * NS + i], acc[i]);
    }
#pragma unroll
    for (int i = 0; i < NS; i++) acc[i] = __fadd_rn(acc[i], sb2[i]);

    float m = acc[0];
#pragma unroll
    for (int i = 1; i < NS; i++) m = fmaxf(m, acc[i]);

    float sh[NS];
    float s = 0.0f;
#pragma unroll
    for (int i = 0; i < NS; i++) {
        sh[i] = __fadd_rn(acc[i], -m);
        s = __fadd_rn(s, expf(sh[i]));
    }
    float L = logf(s);

    float np[NS];
#pragma unroll
    for (int i = 0; i < NS; i++) np[i] = __fadd_rn(L, -sh[i]);   // negated prior

    float4* rec = (float4*)(g_np + (size_t)(t >> 1) * 32);
    if ((t & 1) == 0) {
        rec[0] = make_float4(np[0],  np[1],  np[2],  np[3]);    // lane0 stage1 AB
        rec[1] = make_float4(np[8],  np[9],  np[10], np[11]);   // lane0 stage1 CD
        rec[4] = make_float4(np[5],  np[4],  np[7],  np[6]);    // lane1 stage1 AB
        rec[5] = make_float4(np[13], np[12], np[15], np[14]);   // lane1 stage1 CD
    } else {
        rec[2] = make_float4(np[0],  np[1],  np[8],  np[9]);    // lane0 stage2 g0,g1
        rec[3] = make_float4(np[4],  np[5],  np[12], np[13]);   // lane0 stage2 g2,g3
        rec[6] = make_float4(np[10], np[11], np[2],  np[3]);    // lane1 stage2 g0,g1
        rec[7] = make_float4(np[14], np[15], np[6],  np[7]);    // lane1 stage2 g2,g3
    }
}

// ================= K2: exact sequential scan, 2-lane split =================
// Warp 0: lanes 0/1 each hold 4 of the 8 states:
//   lane0 (u0..u3) = (p0,p1,p2,p3);  lane1 = (p5,p4,p7,p6)
// Per double-step: stage1 pn's (4 per lane), stage2 products (4 per lane),
// then 2x shfl.bfly exchanges g1,g3. All asymmetry is baked into the prior
// layout; every FADD/FMNMX matches the reference op bit-exactly (FMNMX is
// commutative on finite values). Lanes 2-31 mirror lanes 0/1 (same smem
// addresses -> broadcast; results unused).
// Warps 1-3: stage priors global->smem ring.
__global__ void __launch_bounds__(128, 1) k_scan() {
    __shared__ __align__(16) float ring[RB * BS * 16];   // 32 KB
    __shared__ int flag[RB];
    __shared__ int consumed;

    const int tid  = threadIdx.x;
    const int wid  = tid >> 5;
    const int lane = tid & 31;

    if (tid < RB) flag[tid] = 0;
    if (tid == 0) consumed = 0;
    __syncthreads();

    if (wid == 0) {
        const int L = lane & 1;
        float u0 = 0.f, u1 = 0.f, u2 = 0.f, u3 = 0.f;
        for (int b = 0; b < NBLK; b++) {
            if (lane < 2) {
                *(float4*)(g_ckpt + (size_t)b * 8 + L * 4) = make_float4(u0, u1, u2, u3);
            }
            while (ld_acq(&flag[b & (RB - 1)]) != b + 1) { }
            const float4* base = (const float4*)(&ring[(b & (RB - 1)) * (BS * 16)] + L * 16);
#pragma unroll 8
            for (int r = 0; r < BS / 2; r++) {
                float4 q0 = base[r * 8 + 0];
                float4 q1 = base[r * 8 + 1];
                float4 q2 = base[r * 8 + 2];
                float4 q3 = base[r * 8 + 3];
                // stage1 (step t)
                float A = fminf(__fadd_rn(u0, q0.x), __fadd_rn(u1, q0.y));
                float B = fminf(__fadd_rn(u2, q0.z), __fadd_rn(u3, q0.w));
                float C = fminf(__fadd_rn(u0, q1.x), __fadd_rn(u1, q1.y));
                float D = fminf(__fadd_rn(u2, q1.z), __fadd_rn(u3, q1.w));
                // stage2 (step t+1)
                float g0 = fminf(__fadd_rn(A, q2.x), __fadd_rn(B, q2.y));
                float g1 = fminf(__fadd_rn(A, q2.z), __fadd_rn(B, q2.w));
                float g2 = fminf(__fadd_rn(C, q3.x), __fadd_rn(D, q3.y));
                float g3 = fminf(__fadd_rn(C, q3.z), __fadd_rn(D, q3.w));
                // exchange: swap g1,g3 between lane pairs
                u1 = __shfl_xor_sync(0xffffffffu, g1, 1);
                u3 = __shfl_xor_sync(0xffffffffu, g3, 1);
                u0 = g0; u2 = g2;
            }
            if (lane == 0) st_rel(&consumed, b + 1);
        }
    } else {
        // copier warps: wid 1..3 handle blocks b with b % 3 == wid-1
        for (int b = wid - 1; b < NBLK; b += 3) {
            while (b >= RB && ld_acq(&consumed) < b - RB + 1) __nanosleep(100);
            const float4* src = (const float4*)(g_np + (size_t)b * (BS * 16));
            float4* dst = (float4*)&ring[(b & (RB - 1)) * (BS * 16)];
#pragma unroll
            for (int r = 0; r < 8; r++) dst[r * 32 + lane] = src[r * 32 + lane];
            __syncwarp();
            if (lane == 0) st_rel(&flag[b & (RB - 1)], b + 1);
        }
    }
}

// ================= K3: parallel det/conf emission =================
// Each thread replays one 64-step chunk bit-exactly from its checkpoint.
// ckpt: [p0,p1,p2,p3, p5,p4,p7,p6]. np reconstructed from the permuted
// double-step records.
__global__ void k_emit(float* __restrict__ out_det, float* __restrict__ out_conf) {
    int c = blockIdx.x * blockDim.x + threadIdx.x;
    if (c >= NBLK) return;

    float p[8];
    {
        float4 a = *(const float4*)(g_ckpt + (size_t)c * 8);
        float4 b = *(const float4*)(g_ckpt + (size_t)c * 8 + 4);
        p[0] = a.x; p[1] = a.y; p[2] = a.z; p[3] = a.w;
        p[4] = b.y; p[5] = b.x; p[6] = b.w; p[7] = b.z;
    }

    const float4* rec = (const float4*)(g_np + (size_t)c * (BS * 16));
    const int tbase = c * BS;

    for (int r = 0; r < BS / 2; r++) {
        float4 v0 = rec[r * 8 + 0], v1 = rec[r * 8 + 1];
        float4 v2 = rec[r * 8 + 2], v3 = rec[r * 8 + 3];
        float4 v4 = rec[r * 8 + 4], v5 = rec[r * 8 + 5];
        float4 v6 = rec[r * 8 + 6], v7 = rec[r * 8 + 7];

        float nvA[16] = { v0.x, v0.y, v0.z, v0.w,          // np[t][0..3]
                          v4.y, v4.x, v4.w, v4.z,          // np[t][4..7]
                          v1.x, v1.y, v1.z, v1.w,          // np[t][8..11]
                          v5.y, v5.x, v5.w, v5.z };        // np[t][12..15]
        float nvB[16] = { v2.x, v2.y, v6.z, v6.w,          // np[t+1][0..3]
                          v3.x, v3.y, v7.z, v7.w,          // np[t+1][4..7]
                          v2.z, v2.w, v6.x, v6.y,          // np[t+1][8..11]
                          v3.z, v3.w, v7.x, v7.y };        // np[t+1][12..15]

#pragma unroll
        for (int half = 0; half < 2; half++) {
            const float* nv = half ? nvB : nvA;
            // det: first-index argmin over p[0..7], parity
            float best = p[0];
            int idx = 0;
#pragma unroll
            for (int j = 1; j < 8; j++) {
                if (p[j] < best) { best = p[j]; idx = j; }
            }
            // conf: S = sum over 16 duplicated exps, sequential ascending
            float e[8];
#pragma unroll
            for (int j = 0; j < 8; j++) e[j] = expf(__fadd_rn(best, -p[j]));
            float S = e[0];
#pragma unroll
            for (int j = 1; j < 8; j++) S = __fadd_rn(S, e[j]);
#pragma unroll
            for (int j = 0; j < 8; j++) S = __fadd_rn(S, e[j]);
            float conf = __fdiv_rn(1.0f, S);

            int k = r * 2 + half;
            out_det[tbase + k]  = (float)(idx & 1);
            out_conf[tbase + k] = __fmul_rn(2.0f, conf);

            // update: p_new[i] = min(p[2i&7] + np[2i], p[(2i&7)+1] + np[2i+1])
            float newp[8];
#pragma unroll
            for (int i = 0; i < 8; i++) {
                int a2 = (2 * i) & 7;
                newp[i] = fminf(__fadd_rn(p[a2],     nv[2 * i]),
                                __fadd_rn(p[a2 + 1], nv[2 * i + 1]));
            }
#pragma unroll
            for (int i = 0; i < 8; i++) p[i] = newp[i];
        }
    }
}

// ================= launch =================
extern "C" void kernel_launch(void* const* d_in, const int* in_sizes, int n_in,
                              void* d_out, int out_size) {
    const float* rx = (const float*)d_in[0];
    const float* W1 = (const float*)d_in[1];
    const float* b1 = (const float*)d_in[2];
    const float* W2 = (const float*)d_in[3];
    const float* b2 = (const float*)d_in[4];
    float* out = (float*)d_out;

    int T = in_sizes[0];
    if (T > T_LEN) T = T_LEN;

    k_priors<<<(T + 255) / 256, 256>>>(rx, W1, b1, W2, b2, T);
    k_scan<<<1, 128>>>();
    k_emit<<<(NBLK + 127) / 128, 128>>>(out, out + T);
}